// round 9
// baseline (speedup 1.0000x reference)
#include <cuda_runtime.h>
#include <cstdint>
#include <cstddef>

#define N 8192
#define D 64

// ---- k2 config ----
#define JS 8                   // j-splits for gather/partials
#define JRANGE (N / JS)        // 1024
#define CJ 128                 // j's per chunk
#define NCHUNKS_TOTAL (N / CJ) // 64 global chunks
#define NCHUNK (JRANGE / CJ)   // 8 chunks per gather CTA
#define TIB 128                // gather: A-columns per CTA
#define ITILE 1024             // k2a: columns per CTA

// scratch (static device arrays: allocation-free per harness rules)
__device__ float g_y[N * D];                      // y = x@W_nobj + b_nobj (2 MB)
__device__ float g_part[JS][N * D];               // j-split partials (16.8 MB)
__device__ uint4 g_mask[NCHUNKS_TOTAL * N];       // bitmask per (chunk, column) (8.4 MB)

// ---------------------------------------------------------------------------
// Kernel 1: out = x@(W_obj+W_skip) + r@W_rel + biases ;  g_y = x@W_nobj+b_nobj
// ---------------------------------------------------------------------------
__global__ __launch_bounds__(128) void k1_proj(
    const float* __restrict__ x, const float* __restrict__ r,
    const float* __restrict__ W_obj, const float* __restrict__ b_obj,
    const float* __restrict__ W_nobj, const float* __restrict__ b_nobj,
    const float* __restrict__ W_rel, const float* __restrict__ b_rel,
    const float* __restrict__ W_skip, const float* __restrict__ b_skip,
    float* __restrict__ out)
{
    __shared__ float Wc[D * D];
    __shared__ float Wn[D * D];
    __shared__ float Wr[D * D];

    const int t = threadIdx.x;
    for (int e = t; e < D * D; e += 128) {
        Wc[e] = W_obj[e] + W_skip[e];
        Wn[e] = W_nobj[e];
        Wr[e] = W_rel[e];
    }
    __syncthreads();

    const int row = blockIdx.x * 16 + (t >> 3);
    const int d0 = (t & 7) * 8;

    float ab[8], ay[8];
#pragma unroll
    for (int q = 0; q < 8; q++) { ab[q] = 0.f; ay[q] = 0.f; }

    const float4* xp = (const float4*)(x + row * D);
    const float4* rp = (const float4*)(r + row * D);

#pragma unroll 4
    for (int k4 = 0; k4 < D / 4; k4++) {
        const float4 xq = xp[k4];
        const float4 rq = rp[k4];
        const float xv[4] = {xq.x, xq.y, xq.z, xq.w};
        const float rv[4] = {rq.x, rq.y, rq.z, rq.w};
#pragma unroll
        for (int u = 0; u < 4; u++) {
            const int k = k4 * 4 + u;
            const float4 c0 = *(const float4*)&Wc[k * D + d0];
            const float4 c1 = *(const float4*)&Wc[k * D + d0 + 4];
            const float4 n0 = *(const float4*)&Wn[k * D + d0];
            const float4 n1 = *(const float4*)&Wn[k * D + d0 + 4];
            const float4 q0 = *(const float4*)&Wr[k * D + d0];
            const float4 q1 = *(const float4*)&Wr[k * D + d0 + 4];
            const float cc[8] = {c0.x,c0.y,c0.z,c0.w,c1.x,c1.y,c1.z,c1.w};
            const float nn[8] = {n0.x,n0.y,n0.z,n0.w,n1.x,n1.y,n1.z,n1.w};
            const float qq[8] = {q0.x,q0.y,q0.z,q0.w,q1.x,q1.y,q1.z,q1.w};
#pragma unroll
            for (int q = 0; q < 8; q++) {
                ab[q] += xv[u] * cc[q] + rv[u] * qq[q];
                ay[q] += xv[u] * nn[q];
            }
        }
    }

    float4 o0, o1, y0, y1;
    o0.x = ab[0]+b_obj[d0+0]+b_skip[d0+0]+b_rel[d0+0];
    o0.y = ab[1]+b_obj[d0+1]+b_skip[d0+1]+b_rel[d0+1];
    o0.z = ab[2]+b_obj[d0+2]+b_skip[d0+2]+b_rel[d0+2];
    o0.w = ab[3]+b_obj[d0+3]+b_skip[d0+3]+b_rel[d0+3];
    o1.x = ab[4]+b_obj[d0+4]+b_skip[d0+4]+b_rel[d0+4];
    o1.y = ab[5]+b_obj[d0+5]+b_skip[d0+5]+b_rel[d0+5];
    o1.z = ab[6]+b_obj[d0+6]+b_skip[d0+6]+b_rel[d0+6];
    o1.w = ab[7]+b_obj[d0+7]+b_skip[d0+7]+b_rel[d0+7];
    y0.x = ay[0]+b_nobj[d0+0]; y0.y = ay[1]+b_nobj[d0+1];
    y0.z = ay[2]+b_nobj[d0+2]; y0.w = ay[3]+b_nobj[d0+3];
    y1.x = ay[4]+b_nobj[d0+4]; y1.y = ay[5]+b_nobj[d0+5];
    y1.z = ay[6]+b_nobj[d0+6]; y1.w = ay[7]+b_nobj[d0+7];
    float4* op = (float4*)(out + row * D + d0);
    float4* yp = (float4*)(g_y + row * D + d0);
    op[0] = o0; op[1] = o1;
    yp[0] = y0; yp[1] = y1;
}

// ---------------------------------------------------------------------------
// Kernel 2a v4: ROW-CONTIGUOUS A scan + ballot bit-transpose.
// CTA = (1024-column i-tile) x (128-j chunk), 256 threads (8 warps).
// Phase 1: warp w walks rows j = w*16..w*16+15; per row, 32 contiguous 128B
//   LDG.32 rounds; ballot -> word per (j, i-group-of-32); lane g keeps round
//   g's word -> one coalesced STS per row. Per-warp address stream is fully
//   sequential within each 1KB row segment (DRAM page friendly).
// Phase 2: 32x32 bit transpose via 32 ballots per (j32, i32) block ->
//   per-column j-masks, bounced through smem, stored as coalesced uint4.
// Mask semantics match k2b: uint4 component = j32 block, bit = j%32.
// ---------------------------------------------------------------------------
__global__ __launch_bounds__(256) void k2a_scan(const float* __restrict__ A)
{
    __shared__ unsigned bm[32 * 128];     // [i32 group][j]  16 KB
    __shared__ unsigned cm[ITILE * 4];    // [i_local][j32]  16 KB

    const int t = threadIdx.x;
    const int w = t >> 5, lane = t & 31;
    const int chunk = blockIdx.y;                   // 0..63
    const int i0 = blockIdx.x * ITILE;

    // ---- phase 1: row-contiguous scan, ballot per 32 columns ----
#pragma unroll
    for (int rr = 0; rr < 16; rr++) {
        const int j = w * 16 + rr;                  // 0..127
        const float* row = A + (size_t)(chunk * CJ + j) * N + i0 + lane;
        unsigned mine = 0;
#pragma unroll
        for (int g = 0; g < 32; g++) {              // 32 x 128B contiguous
            const float v = __ldcs(row + g * 32);
            const unsigned word = __ballot_sync(0xFFFFFFFFu, v != 0.0f);
            if (lane == g) mine = word;             // lane g owns group g
        }
        bm[lane * 128 + j] = mine;                  // coalesced STS
    }
    __syncthreads();

    // ---- phase 2: 32x32 bit transpose (32 ballots per block) ----
    // tasks: (g in 0..31) x (j32 in 0..3) = 128; 8 warps -> 16 each
#pragma unroll
    for (int task = 0; task < 16; task++) {
        const int tid = w * 16 + task;
        const int g = tid >> 2;                     // i-group 0..31
        const int j32 = tid & 3;                    // j-word 0..3
        const unsigned wj = bm[g * 128 + j32 * 32 + lane];   // lane = j in block
        unsigned keep = 0;
#pragma unroll
        for (int b = 0; b < 32; b++) {
            const unsigned m = __ballot_sync(0xFFFFFFFFu, (wj >> b) & 1u);
            if (lane == b) keep = m;                // lane b owns column g*32+b
        }
        cm[(g * 32 + lane) * 4 + j32] = keep;
    }
    __syncthreads();

    // ---- coalesced uint4 mask store ----
    uint4* mp = g_mask + (size_t)chunk * N + i0;
    const uint4* cm4 = (const uint4*)cm;
#pragma unroll
    for (int e = 0; e < ITILE / 256; e++)           // 4 per thread
        mp[e * 256 + t] = cm4[e * 256 + t];
}

// ---------------------------------------------------------------------------
// Kernel 2b: gather. CTA = 128 rows (i) x one j-split. Per chunk: stage y
// (32 KB), warp walks its 32 rows via broadcast uint4 mask + ffs,
// lane owns a d-pair; conflict-free LDS.64; register accumulators.
// ---------------------------------------------------------------------------
__global__ __launch_bounds__(128, 4) void k2b_gather()
{
    __shared__ float y_s[CJ * D];   // 32 KB

    const int t = threadIdx.x;
    const int w = t >> 5, lane = t & 31;
    const int i_base = blockIdx.x * TIB;
    const int jy = blockIdx.y;
    const size_t j_base = (size_t)jy * JRANGE;

    float accx[32], accy[32];
#pragma unroll
    for (int il = 0; il < 32; il++) { accx[il] = 0.f; accy[il] = 0.f; }

    for (int c = 0; c < NCHUNK; c++) {
        {
            const float4* ys = (const float4*)(g_y + (j_base + c * CJ) * D);
            float4* yd = (float4*)y_s;
#pragma unroll
            for (int e = 0; e < (CJ * D / 4) / 128; e++)   // 16
                yd[e * 128 + t] = ys[e * 128 + t];
        }
        __syncthreads();

        const int chunk = jy * NCHUNK + c;                 // global chunk
        const uint4* mrow = g_mask + (size_t)chunk * N + i_base;
        const float2* y2 = (const float2*)y_s;

#pragma unroll 4
        for (int il = 0; il < 32; il++) {
            const int iloc = (w << 5) | il;
            const uint4 mv = __ldg(mrow + iloc);           // uniform per warp
            float ax = 0.f, ay = 0.f;
            const unsigned mwords[4] = {mv.x, mv.y, mv.z, mv.w};
#pragma unroll
            for (int k4 = 0; k4 < 4; k4++) {
                unsigned mm = mwords[k4];
                while (mm) {
                    const int b = __ffs(mm) - 1;
                    mm &= mm - 1;
                    const float2 v = y2[(k4 * 32 + b) * 32 + lane];
                    ax += v.x; ay += v.y;
                }
            }
            accx[il] += ax;
            accy[il] += ay;
        }
        __syncthreads();   // y_s free for restage
    }

#pragma unroll
    for (int il = 0; il < 32; il++) {
        const int i = i_base + (w << 5) + il;
        ((float2*)&g_part[jy][(size_t)i * D])[lane] = make_float2(accx[il], accy[il]);
    }
}

// ---------------------------------------------------------------------------
// Kernel 3: out += sum over the JS partials (fixed order -> deterministic)
// ---------------------------------------------------------------------------
__global__ __launch_bounds__(256) void k3_reduce(float* __restrict__ out)
{
    const int g = blockIdx.x * blockDim.x + threadIdx.x;
    float4 v = ((const float4*)out)[g];
#pragma unroll
    for (int s = 0; s < JS; s++) {
        const float4 p = ((const float4*)(&g_part[s][0]))[g];
        v.x += p.x; v.y += p.y; v.z += p.z; v.w += p.w;
    }
    ((float4*)out)[g] = v;
}

// ---------------------------------------------------------------------------
extern "C" void kernel_launch(void* const* d_in, const int* in_sizes, int n_in,
                              void* d_out, int out_size)
{
    const float* x      = (const float*)d_in[0];
    const float* r      = (const float*)d_in[1];
    const float* A      = (const float*)d_in[2];
    const float* W_obj  = (const float*)d_in[3];
    const float* b_obj  = (const float*)d_in[4];
    const float* W_nobj = (const float*)d_in[5];
    const float* b_nobj = (const float*)d_in[6];
    const float* W_rel  = (const float*)d_in[7];
    const float* b_rel  = (const float*)d_in[8];
    const float* W_skip = (const float*)d_in[9];
    const float* b_skip = (const float*)d_in[10];
    // d_in[11]/d_in[12] (Wa_w, Wa_b) provably cancel: softmax rows sum to 1,
    // so the attention term is the identity on `aggregated`.
    float* out = (float*)d_out;

    k2a_scan<<<dim3(N / ITILE, NCHUNKS_TOTAL), 256>>>(A);   // longest stream first
    k1_proj<<<N / 16, 128>>>(x, r, W_obj, b_obj, W_nobj, b_nobj,
                             W_rel, b_rel, W_skip, b_skip, out);
    k2b_gather<<<dim3(N / TIB, JS), 128>>>();
    k3_reduce<<<(N * D / 4) / 256, 256>>>(out);
}

// round 10
// speedup vs baseline: 1.5360x; 1.5360x over previous
#include <cuda_runtime.h>
#include <cstdint>
#include <cstddef>

#define N 8192
#define D 64

// ---- k2 config ----
#define JS 8                   // j-splits for gather/partials
#define JRANGE (N / JS)        // 1024
#define CJ 128                 // j's per chunk
#define NCHUNKS_TOTAL (N / CJ) // 64 global chunks
#define NCHUNK (JRANGE / CJ)   // 8 chunks per gather CTA
#define TIB 128                // gather: A-columns per CTA
#define ITILE 1024             // k2a: columns per CTA (256 thr x 4 cols)

// scratch (static device arrays: allocation-free per harness rules)
__device__ float g_y[N * D];                      // y = x@W_nobj + b_nobj (2 MB)
__device__ float g_part[JS][N * D];               // j-split partials (16.8 MB)
__device__ uint4 g_mask[NCHUNKS_TOTAL * N];       // bitmask per (chunk, column) (8.4 MB)

// ---------------------------------------------------------------------------
// Kernel 1: out = x@(W_obj+W_skip) + r@W_rel + biases ;  g_y = x@W_nobj+b_nobj
// ---------------------------------------------------------------------------
__global__ __launch_bounds__(128) void k1_proj(
    const float* __restrict__ x, const float* __restrict__ r,
    const float* __restrict__ W_obj, const float* __restrict__ b_obj,
    const float* __restrict__ W_nobj, const float* __restrict__ b_nobj,
    const float* __restrict__ W_rel, const float* __restrict__ b_rel,
    const float* __restrict__ W_skip, const float* __restrict__ b_skip,
    float* __restrict__ out)
{
    __shared__ float Wc[D * D];
    __shared__ float Wn[D * D];
    __shared__ float Wr[D * D];

    const int t = threadIdx.x;
    for (int e = t; e < D * D; e += 128) {
        Wc[e] = W_obj[e] + W_skip[e];
        Wn[e] = W_nobj[e];
        Wr[e] = W_rel[e];
    }
    __syncthreads();

    const int row = blockIdx.x * 16 + (t >> 3);
    const int d0 = (t & 7) * 8;

    float ab[8], ay[8];
#pragma unroll
    for (int q = 0; q < 8; q++) { ab[q] = 0.f; ay[q] = 0.f; }

    const float4* xp = (const float4*)(x + row * D);
    const float4* rp = (const float4*)(r + row * D);

#pragma unroll 4
    for (int k4 = 0; k4 < D / 4; k4++) {
        const float4 xq = xp[k4];
        const float4 rq = rp[k4];
        const float xv[4] = {xq.x, xq.y, xq.z, xq.w};
        const float rv[4] = {rq.x, rq.y, rq.z, rq.w};
#pragma unroll
        for (int u = 0; u < 4; u++) {
            const int k = k4 * 4 + u;
            const float4 c0 = *(const float4*)&Wc[k * D + d0];
            const float4 c1 = *(const float4*)&Wc[k * D + d0 + 4];
            const float4 n0 = *(const float4*)&Wn[k * D + d0];
            const float4 n1 = *(const float4*)&Wn[k * D + d0 + 4];
            const float4 q0 = *(const float4*)&Wr[k * D + d0];
            const float4 q1 = *(const float4*)&Wr[k * D + d0 + 4];
            const float cc[8] = {c0.x,c0.y,c0.z,c0.w,c1.x,c1.y,c1.z,c1.w};
            const float nn[8] = {n0.x,n0.y,n0.z,n0.w,n1.x,n1.y,n1.z,n1.w};
            const float qq[8] = {q0.x,q0.y,q0.z,q0.w,q1.x,q1.y,q1.z,q1.w};
#pragma unroll
            for (int q = 0; q < 8; q++) {
                ab[q] += xv[u] * cc[q] + rv[u] * qq[q];
                ay[q] += xv[u] * nn[q];
            }
        }
    }

    float4 o0, o1, y0, y1;
    o0.x = ab[0]+b_obj[d0+0]+b_skip[d0+0]+b_rel[d0+0];
    o0.y = ab[1]+b_obj[d0+1]+b_skip[d0+1]+b_rel[d0+1];
    o0.z = ab[2]+b_obj[d0+2]+b_skip[d0+2]+b_rel[d0+2];
    o0.w = ab[3]+b_obj[d0+3]+b_skip[d0+3]+b_rel[d0+3];
    o1.x = ab[4]+b_obj[d0+4]+b_skip[d0+4]+b_rel[d0+4];
    o1.y = ab[5]+b_obj[d0+5]+b_skip[d0+5]+b_rel[d0+5];
    o1.z = ab[6]+b_obj[d0+6]+b_skip[d0+6]+b_rel[d0+6];
    o1.w = ab[7]+b_obj[d0+7]+b_skip[d0+7]+b_rel[d0+7];
    y0.x = ay[0]+b_nobj[d0+0]; y0.y = ay[1]+b_nobj[d0+1];
    y0.z = ay[2]+b_nobj[d0+2]; y0.w = ay[3]+b_nobj[d0+3];
    y1.x = ay[4]+b_nobj[d0+4]; y1.y = ay[5]+b_nobj[d0+5];
    y1.z = ay[6]+b_nobj[d0+6]; y1.w = ay[7]+b_nobj[d0+7];
    float4* op = (float4*)(out + row * D + d0);
    float4* yp = (float4*)(g_y + row * D + d0);
    op[0] = o0; op[1] = o1;
    yp[0] = y0; yp[1] = y1;
}

// ---------------------------------------------------------------------------
// Kernel 2a v5: row-contiguous A scan, per-thread REGISTER masks.
// Thread owns 4 consecutive columns (one float4 per row). Warp reads 512B
// contiguous per row; CTA reads 4KB per row (thread-linear, k3-class stream).
// Masks built with scalar FSETP/LOP3 only — no ballots, no smem, no phase 2.
// Batch-of-8 rows in flight (32 buffer regs). Mask layout matches k2b:
// uint4 per column; component = j-word (j/32), bit = j%32.
// ---------------------------------------------------------------------------
__global__ __launch_bounds__(256) void k2a_scan(const float* __restrict__ A)
{
    const int t = threadIdx.x;
    const int chunk = blockIdx.y;                       // 0..63
    const int i0 = blockIdx.x * ITILE + 4 * t;          // 4 owned columns
    const int rs = N / 4;                               // row stride (float4)
    const float4* Ap = (const float4*)A + (size_t)chunk * CJ * rs + (i0 >> 2);

    unsigned m[4][4];                                   // [j-word][col]
#pragma unroll
    for (int a = 0; a < 4; a++)
#pragma unroll
        for (int b = 0; b < 4; b++) m[a][b] = 0u;

#pragma unroll
    for (int jw = 0; jw < 4; jw++) {                    // 4 j-words
#pragma unroll
        for (int jb = 0; jb < 32; jb += 8) {            // batches of 8 rows
            float4 v[8];
#pragma unroll
            for (int u = 0; u < 8; u++)                 // 8 independent LDG.128
                v[u] = __ldcs(Ap + (size_t)(jw * 32 + jb + u) * rs);
#pragma unroll
            for (int u = 0; u < 8; u++) {
                const unsigned bit = 1u << (jb + u);    // compile-time
                if (v[u].x != 0.0f) m[jw][0] |= bit;
                if (v[u].y != 0.0f) m[jw][1] |= bit;
                if (v[u].z != 0.0f) m[jw][2] |= bit;
                if (v[u].w != 0.0f) m[jw][3] |= bit;
            }
        }
    }

    uint4* mp = g_mask + (size_t)chunk * N + i0;        // per-column uint4
#pragma unroll
    for (int c = 0; c < 4; c++)
        mp[c] = make_uint4(m[0][c], m[1][c], m[2][c], m[3][c]);
}

// ---------------------------------------------------------------------------
// Kernel 2b: gather. CTA = 128 rows (i) x one j-split. Per chunk: stage y
// (32 KB), warp walks its 32 rows via broadcast uint4 mask + ffs,
// lane owns a d-pair; conflict-free LDS.64; register accumulators.
// ---------------------------------------------------------------------------
__global__ __launch_bounds__(128, 4) void k2b_gather()
{
    __shared__ float y_s[CJ * D];   // 32 KB

    const int t = threadIdx.x;
    const int w = t >> 5, lane = t & 31;
    const int i_base = blockIdx.x * TIB;
    const int jy = blockIdx.y;
    const size_t j_base = (size_t)jy * JRANGE;

    float accx[32], accy[32];
#pragma unroll
    for (int il = 0; il < 32; il++) { accx[il] = 0.f; accy[il] = 0.f; }

    for (int c = 0; c < NCHUNK; c++) {
        {
            const float4* ys = (const float4*)(g_y + (j_base + c * CJ) * D);
            float4* yd = (float4*)y_s;
#pragma unroll
            for (int e = 0; e < (CJ * D / 4) / 128; e++)   // 16
                yd[e * 128 + t] = ys[e * 128 + t];
        }
        __syncthreads();

        const int chunk = jy * NCHUNK + c;                 // global chunk
        const uint4* mrow = g_mask + (size_t)chunk * N + i_base;
        const float2* y2 = (const float2*)y_s;

#pragma unroll 4
        for (int il = 0; il < 32; il++) {
            const int iloc = (w << 5) | il;
            const uint4 mv = __ldg(mrow + iloc);           // uniform per warp
            float ax = 0.f, ay = 0.f;
            const unsigned mwords[4] = {mv.x, mv.y, mv.z, mv.w};
#pragma unroll
            for (int k4 = 0; k4 < 4; k4++) {
                unsigned mm = mwords[k4];
                while (mm) {
                    const int b = __ffs(mm) - 1;
                    mm &= mm - 1;
                    const float2 v = y2[(k4 * 32 + b) * 32 + lane];
                    ax += v.x; ay += v.y;
                }
            }
            accx[il] += ax;
            accy[il] += ay;
        }
        __syncthreads();   // y_s free for restage
    }

#pragma unroll
    for (int il = 0; il < 32; il++) {
        const int i = i_base + (w << 5) + il;
        ((float2*)&g_part[jy][(size_t)i * D])[lane] = make_float2(accx[il], accy[il]);
    }
}

// ---------------------------------------------------------------------------
// Kernel 3: out += sum over the JS partials (fixed order -> deterministic)
// ---------------------------------------------------------------------------
__global__ __launch_bounds__(256) void k3_reduce(float* __restrict__ out)
{
    const int g = blockIdx.x * blockDim.x + threadIdx.x;
    float4 v = ((const float4*)out)[g];
#pragma unroll
    for (int s = 0; s < JS; s++) {
        const float4 p = ((const float4*)(&g_part[s][0]))[g];
        v.x += p.x; v.y += p.y; v.z += p.z; v.w += p.w;
    }
    ((float4*)out)[g] = v;
}

// ---------------------------------------------------------------------------
extern "C" void kernel_launch(void* const* d_in, const int* in_sizes, int n_in,
                              void* d_out, int out_size)
{
    const float* x      = (const float*)d_in[0];
    const float* r      = (const float*)d_in[1];
    const float* A      = (const float*)d_in[2];
    const float* W_obj  = (const float*)d_in[3];
    const float* b_obj  = (const float*)d_in[4];
    const float* W_nobj = (const float*)d_in[5];
    const float* b_nobj = (const float*)d_in[6];
    const float* W_rel  = (const float*)d_in[7];
    const float* b_rel  = (const float*)d_in[8];
    const float* W_skip = (const float*)d_in[9];
    const float* b_skip = (const float*)d_in[10];
    // d_in[11]/d_in[12] (Wa_w, Wa_b) provably cancel: softmax rows sum to 1,
    // so the attention term is the identity on `aggregated`.
    float* out = (float*)d_out;

    k2a_scan<<<dim3(N / ITILE, NCHUNKS_TOTAL), 256>>>(A);   // longest stream first
    k1_proj<<<N / 16, 128>>>(x, r, W_obj, b_obj, W_nobj, b_nobj,
                             W_rel, b_rel, W_skip, b_skip, out);
    k2b_gather<<<dim3(N / TIB, JS), 128>>>();
    k3_reduce<<<(N * D / 4) / 256, 256>>>(out);
}